// round 16
// baseline (speedup 1.0000x reference)
#include <cuda_runtime.h>
#include <cuda.h>
#include <cuda_fp16.h>
#include <cstdint>
#include <cmath>

// Problem constants
#define BB   8
#define TT   4096
#define DD   256
#define MTOT (BB*TT)        // 32768
#define KTOT 512            // 2 taps x 256
#define NSEG 256
#define SEGL (TT/NSEG)      // 16

// GEMM tiling: fp16, BK=64 halves, R11 consumer geometry, TMA producer, persistent
#define BM 128
#define BN 128
#define NKB 8               // stages per tile
#define STAGES 3
#define A_BYTES (BM*128)            // 16384
#define B_BYTES (BN*128)            // 16384
#define STAGE_BYTES (A_BYTES+B_BYTES)   // 32768
#define STAGE_TX STAGE_BYTES
#define DYN_SMEM (STAGES*STAGE_BYTES + 1024)   // 99328; 2 CTAs/SM

#define NTILE_N 6
#define NTILES  (NTILE_N * (MTOT/BM))   // 1536
#define GRID_P  296                      // 2 CTAs x 148 SMs
#define EXTRA   (NTILES - 5*GRID_P)      // 56 CTAs do 6 tiles, rest do 5

// ---------------- scratch (device globals) ----------------
__device__ __half g_zh[(size_t)MTOT*DD];
__device__ __half g_fh[(size_t)MTOT*DD];
__device__ __half g_oh[(size_t)MTOT*DD];
__device__ __half g_xh[(size_t)MTOT*DD];
__device__ __half g_wh[3*DD*KTOT];
__device__ float  g_segA[BB*NSEG*DD];
__device__ float  g_segB[BB*NSEG*DD];
__device__ float  g_carry[BB*NSEG*DD];

// ---------------- helpers ----------------
__device__ __forceinline__ uint32_t smem_u32(const void* p) {
    uint32_t a;
    asm("{ .reg .u64 t; cvta.to.shared.u64 t, %1; cvt.u32.u64 %0, t; }" : "=r"(a) : "l"(p));
    return a;
}
__device__ __forceinline__ void ldsm4(uint32_t& r0, uint32_t& r1, uint32_t& r2, uint32_t& r3,
                                      uint32_t addr) {
    asm volatile("ldmatrix.sync.aligned.m8n8.x4.shared.b16 {%0,%1,%2,%3}, [%4];"
                 : "=r"(r0), "=r"(r1), "=r"(r2), "=r"(r3) : "r"(addr));
}
__device__ __forceinline__ void mma_f16(float c[4], const uint32_t a[4], const uint32_t b[2]) {
    asm("mma.sync.aligned.m16n8k16.row.col.f32.f16.f16.f32 "
        "{%0,%1,%2,%3}, {%4,%5,%6,%7}, {%8,%9}, {%0,%1,%2,%3};"
        : "+f"(c[0]), "+f"(c[1]), "+f"(c[2]), "+f"(c[3])
        : "r"(a[0]), "r"(a[1]), "r"(a[2]), "r"(a[3]), "r"(b[0]), "r"(b[1]));
}
__device__ __forceinline__ void tma_load_2d(uint32_t dst, const void* map, int x, int y,
                                            uint32_t mbar) {
    asm volatile(
        "cp.async.bulk.tensor.2d.shared::cta.global.tile.mbarrier::complete_tx::bytes "
        "[%0], [%1, {%2, %3}], [%4];"
        :: "r"(dst), "l"(map), "r"(x), "r"(y), "r"(mbar) : "memory");
}
#define MBARRIER_INIT(addr, cnt) \
    asm volatile("mbarrier.init.shared.b64 [%0], %1;" :: "r"(addr), "r"(cnt) : "memory")
#define MBARRIER_EXPECT_TX(addr, bytes) \
    asm volatile("mbarrier.arrive.expect_tx.shared.b64 _, [%0], %1;" \
                 :: "r"(addr), "r"(bytes) : "memory")
#define FENCE_PROXY_ASYNC() \
    asm volatile("fence.proxy.async.shared::cta;" ::: "memory")
#define MBARRIER_WAIT_PARITY(addr, par) do {                                     \
    uint32_t _m = (addr), _p = (par), _done;                                     \
    asm volatile("{ .reg .pred p; mbarrier.try_wait.parity.acquire.cta.shared::cta.b64 p, [%1], %2;" \
                 " selp.b32 %0, 1, 0, p; }" : "=r"(_done) : "r"(_m), "r"(_p) : "memory"); \
    if (!_done) {                                                                \
        asm volatile("{ .reg .pred P1; WL%=:"                                    \
                     " mbarrier.try_wait.parity.acquire.cta.shared::cta.b64 P1, [%0], %1, 0x989680;" \
                     " @P1 bra.uni WD%=; bra.uni WL%=; WD%=: }"                  \
                     :: "r"(_m), "r"(_p) : "memory");                            \
    } } while (0)

// ---------------- fused prep: x->fp16  +  W transpose->fp16 ----------------
__global__ void prep(const float* __restrict__ x, const float* __restrict__ Wz,
                     const float* __restrict__ Wf, const float* __restrict__ Wo) {
    __shared__ float t[32][33];
    const int bidx = blockIdx.x;
    const int tid  = threadIdx.x;
    if (bidx < (MTOT * DD / 4) / 256) {           // 8192 blocks: x conversion
        size_t i = (size_t)bidx * 256 + tid;
        float4 v = ((const float4*)x)[i];
        ((__half2*)g_xh)[i * 2]     = __floats2half2_rn(v.x, v.y);
        ((__half2*)g_xh)[i * 2 + 1] = __floats2half2_rn(v.z, v.w);
        return;
    }
    // 384 blocks: W transpose (idx = bx + 64*(tap + 2*g))
    const int idx = bidx - (MTOT * DD / 4) / 256;
    const int bx = idx & 63, tap = (idx >> 6) & 1, g = idx >> 7;
    const float* W = (g == 0) ? Wz : (g == 1) ? Wf : Wo;
    const int d0 = (bx & 7) * 32;
    const int n0 = (bx >> 3) * 32;
    const int tx = tid & 31, ty = tid >> 5;
    #pragma unroll
    for (int r = 0; r < 4; r++) {
        int d = d0 + ty + r * 8;
        t[ty + r * 8][tx] = W[(size_t)tap * 65536 + (size_t)d * 256 + n0 + tx];
    }
    __syncthreads();
    #pragma unroll
    for (int r = 0; r < 4; r++) {
        int n = n0 + ty + r * 8;
        g_wh[(size_t)g * (DD * KTOT) + (size_t)n * KTOT + tap * 256 + d0 + tx] =
            __float2half_rn(t[tx][ty + r * 8]);
    }
}

// ---------------- persistent TMA-fed fp16 mma.sync gate GEMM ----------------
// 296 CTAs; each consumes 5-6 (m,n) tiles, TMA pipeline continuous across tiles.
// Tile t: n_idx=t%6 (gate=n_idx>>1, n half), m_idx=t/6. 8 stages per tile.
__global__ __launch_bounds__(256)
void gates_gemm(const __grid_constant__ CUtensorMap tma_a,
                const __grid_constant__ CUtensorMap tma_b,
                const float* __restrict__ bz, const float* __restrict__ bfv,
                const float* __restrict__ bo) {
    extern __shared__ char dyn[];
    __shared__ __align__(8) uint64_t s_mbar[STAGES];
    const uint32_t sbase = (smem_u32(dyn) + 1023u) & ~1023u;
    uint32_t mb[STAGES];
    #pragma unroll
    for (int i = 0; i < STAGES; i++) mb[i] = smem_u32(&s_mbar[i]);

    const int tid  = threadIdx.x;
    const int warp = tid >> 5, lane = tid & 31;
    const int gq = lane >> 2, q = lane & 3;
    const int wm0 = (warp & 1) * 64;
    const int wn0 = (warp >> 1) * 32;
    const int cta = blockIdx.x;
    const int ntl = (cta < EXTRA) ? 6 : 5;         // tiles for this CTA
    const int G   = ntl * NKB;                     // total stages

    if (tid == 0) {
        #pragma unroll
        for (int i = 0; i < STAGES; i++) MBARRIER_INIT(mb[i], 1);
    }
    __syncthreads();

    // stage g -> tile t = cta + (g/8)*296, kb = g%8
    auto issue = [&](int g) {
        const int s  = g % STAGES;
        const int t  = cta + (g >> 3) * GRID_P;
        const int kb = g & 7;
        const int m0 = (t / NTILE_N) * BM;
        MBARRIER_EXPECT_TX(mb[s], STAGE_TX);
        tma_load_2d(sbase + s * STAGE_BYTES, &tma_a,
                    (kb & 3) * 64, m0 - 1 + (kb >> 2), mb[s]);
        tma_load_2d(sbase + s * STAGE_BYTES + A_BYTES, &tma_b,
                    kb * 64, (t % NTILE_N) * 128, mb[s]);
    };

    const int mi1 = (lane >> 3) & 1;
    const int mi2 = lane >> 4;
    const int rr  = lane & 7;

    if (tid == 0) {
        FENCE_PROXY_ASYNC();
        issue(0); issue(1); issue(2);
    }

    int g = 0;
    for (int k = 0; k < ntl; k++) {
        const int t     = cta + k * GRID_P;
        const int n_idx = t % NTILE_N;
        const int m0    = (t / NTILE_N) * BM;
        const int gate  = n_idx >> 1;
        const int n0g   = (n_idx & 1) * 128;
        const bool first_blk = ((m0 & (TT - 1)) == 0);

        float acc[4][4][4];
        #pragma unroll
        for (int mt = 0; mt < 4; mt++)
            #pragma unroll
            for (int nt = 0; nt < 4; nt++)
                #pragma unroll
                for (int i = 0; i < 4; i++) acc[mt][nt][i] = 0.0f;

        #pragma unroll 1
        for (int kb = 0; kb < NKB; kb++, g++) {
            const int s = g % STAGES;
            MBARRIER_WAIT_PARITY(mb[s], (g / STAGES) & 1);
            if (first_blk && kb < 4) {
                // tap0 stage: A row 0 = token m0-1 (prev batch / OOB) -> zero
                if (tid < 8) {
                    const uint32_t a0 = sbase + s * STAGE_BYTES + (tid << 4);
                    asm volatile("st.shared.v4.b32 [%0], {%1,%1,%1,%1};"
                                 :: "r"(a0), "r"(0) : "memory");
                }
                __syncthreads();
            }
            // ---- compute stage (R11 verbatim) ----
            {
                const uint32_t ab = sbase + s * STAGE_BYTES;
                const uint32_t bb = ab + A_BYTES;
                #pragma unroll
                for (int ks = 0; ks < 4; ks++) {
                    uint32_t af[4][4], bf[4][2];
                    #pragma unroll
                    for (int mt = 0; mt < 4; mt++) {
                        int row = wm0 + mt * 16 + mi1 * 8 + rr;
                        int k4  = ks * 2 + mi2;
                        uint32_t addr = ab + (row << 7) + ((k4 ^ (row & 7)) << 4);
                        ldsm4(af[mt][0], af[mt][1], af[mt][2], af[mt][3], addr);
                    }
                    #pragma unroll
                    for (int ntp = 0; ntp < 2; ntp++) {
                        int row = wn0 + ntp * 16 + mi2 * 8 + rr;
                        int k4  = ks * 2 + mi1;
                        uint32_t addr = bb + (row << 7) + ((k4 ^ (row & 7)) << 4);
                        uint32_t r0, r1, r2, r3;
                        ldsm4(r0, r1, r2, r3, addr);
                        bf[2*ntp][0] = r0;   bf[2*ntp][1] = r1;
                        bf[2*ntp+1][0] = r2; bf[2*ntp+1][1] = r3;
                    }
                    #pragma unroll
                    for (int mt = 0; mt < 4; mt++)
                        #pragma unroll
                        for (int nt = 0; nt < 4; nt++)
                            mma_f16(acc[mt][nt], af[mt], bf[nt]);
                }
            }
            __syncthreads();                      // slot s fully consumed
            if (tid == 0 && g + STAGES < G) {
                FENCE_PROXY_ASYNC();
                issue(g + STAGES);
            }
        }

        // ---- epilogue (overlaps next tile's TMA): fast-math activations ----
        const float* bias = (gate == 0) ? bz : (gate == 1) ? bfv : bo;
        __half* dst       = (gate == 0) ? g_zh : (gate == 1) ? g_fh : g_oh;
        #pragma unroll
        for (int mt = 0; mt < 4; mt++) {
            #pragma unroll
            for (int nt = 0; nt < 4; nt++) {
                #pragma unroll
                for (int h = 0; h < 2; h++) {
                    int m  = m0 + wm0 + mt * 16 + gq + h * 8;
                    int n  = n0g + wn0 + nt * 8 + q * 2;
                    float v0 = acc[mt][nt][2*h]   + bias[n];
                    float v1 = acc[mt][nt][2*h+1] + bias[n + 1];
                    if (gate == 0) {   // tanh(v) = 2*sigmoid(2v) - 1, __expf-exact
                        v0 = __fdividef(2.0f, 1.0f + __expf(-2.0f * v0)) - 1.0f;
                        v1 = __fdividef(2.0f, 1.0f + __expf(-2.0f * v1)) - 1.0f;
                    } else {
                        v0 = __fdividef(1.0f, 1.0f + __expf(-v0));
                        v1 = __fdividef(1.0f, 1.0f + __expf(-v1));
                    }
                    *(__half2*)(dst + (size_t)m * DD + n) = __floats2half2_rn(v0, v1);
                }
            }
        }
    }
}

// ---------------- segmented scan: fp16 gates, fp32 math, NSEG=256 ----------------
__global__ void seg_reduce() {
    int tid = blockIdx.x * 256 + threadIdx.x;   // 262144 threads: (b, s, d2)
    int d2 = tid & 127;
    int s  = (tid >> 7) & (NSEG - 1);
    int b  = tid >> 15;
    size_t base2 = (((size_t)b * TT + (size_t)s * SEGL) * DD) / 2 + d2;
    float Ax = 1.0f, Ay = 1.0f, Bx = 0.0f, By = 0.0f;
    #pragma unroll
    for (int i = 0; i < SEGL; i++) {
        float2 f = __half22float2(((const __half2*)g_fh)[base2 + (size_t)i * (DD/2)]);
        float2 z = __half22float2(((const __half2*)g_zh)[base2 + (size_t)i * (DD/2)]);
        Ax *= f.x; Ay *= f.y;
        Bx = f.x * Bx + (1.0f - f.x) * z.x;
        By = f.y * By + (1.0f - f.y) * z.y;
    }
    int sidx = (b * NSEG + s) * (DD/2) + d2;
    ((float2*)g_segA)[sidx] = make_float2(Ax, Ay);
    ((float2*)g_segB)[sidx] = make_float2(Bx, By);
}

__global__ void seg_carry() {
    int tid = blockIdx.x * 256 + threadIdx.x;   // 2048 threads: (b, d)
    int d = tid & 255;
    int b = tid >> 8;
    float c = 0.0f;
    for (int s = 0; s < NSEG; s++) {
        int idx = (b * NSEG + s) * DD + d;
        g_carry[idx] = c;
        c = g_segA[idx] * c + g_segB[idx];
    }
}

__global__ void seg_apply(float* __restrict__ out) {
    int tid = blockIdx.x * 256 + threadIdx.x;   // 262144 threads: (b, s, d2)
    int d2 = tid & 127;
    int s  = (tid >> 7) & (NSEG - 1);
    int b  = tid >> 15;
    size_t base2 = (((size_t)b * TT + (size_t)s * SEGL) * DD) / 2 + d2;
    float2 c = ((const float2*)g_carry)[(b * NSEG + s) * (DD/2) + d2];
    #pragma unroll
    for (int i = 0; i < SEGL; i++) {
        size_t idx = base2 + (size_t)i * (DD/2);
        float2 f = __half22float2(((const __half2*)g_fh)[idx]);
        float2 z = __half22float2(((const __half2*)g_zh)[idx]);
        float2 o = __half22float2(((const __half2*)g_oh)[idx]);
        c.x = f.x * c.x + (1.0f - f.x) * z.x;
        c.y = f.y * c.y + (1.0f - f.y) * z.y;
        ((float2*)out)[idx] = make_float2(o.x * c.x, o.y * c.y);
    }
}

// ---------------- launch ----------------
typedef CUresult (*EncodeFn)(CUtensorMap*, CUtensorMapDataType, cuuint32_t, void*,
                             const cuuint64_t*, const cuuint64_t*, const cuuint32_t*,
                             const cuuint32_t*, CUtensorMapInterleave, CUtensorMapSwizzle,
                             CUtensorMapL2promotion, CUtensorMapFloatOOBfill);

extern "C" void kernel_launch(void* const* d_in, const int* in_sizes, int n_in,
                              void* d_out, int out_size) {
    const float* x   = (const float*)d_in[0];
    const float* Wz  = (const float*)d_in[1];
    const float* Wf  = (const float*)d_in[2];
    const float* Wo  = (const float*)d_in[3];
    const float* bz  = (const float*)d_in[4];
    const float* bfv = (const float*)d_in[5];
    const float* bo  = (const float*)d_in[6];
    float* out = (float*)d_out;

    void* encode_fn = nullptr;
    cudaDriverEntryPointQueryResult qr;
    cudaGetDriverEntryPointByVersion("cuTensorMapEncodeTiled", &encode_fn, 12000,
                                     cudaEnableDefault, &qr);
    void *xa = nullptr, *wa = nullptr;
    cudaGetSymbolAddress(&xa, g_xh);
    cudaGetSymbolAddress(&wa, g_wh);

    CUtensorMap tmap_a, tmap_b;
    {
        cuuint64_t dims[2]    = { 256, 32768 };
        cuuint64_t strides[1] = { 256 * 2 };
        cuuint32_t box[2]     = { 64, 128 };
        cuuint32_t es[2]      = { 1, 1 };
        ((EncodeFn)encode_fn)(&tmap_a, CU_TENSOR_MAP_DATA_TYPE_FLOAT16, 2, xa,
                              dims, strides, box, es,
                              CU_TENSOR_MAP_INTERLEAVE_NONE, CU_TENSOR_MAP_SWIZZLE_128B,
                              CU_TENSOR_MAP_L2_PROMOTION_L2_128B,
                              CU_TENSOR_MAP_FLOAT_OOB_FILL_NONE);
    }
    {
        cuuint64_t dims[2]    = { 512, 768 };
        cuuint64_t strides[1] = { 512 * 2 };
        cuuint32_t box[2]     = { 64, 128 };
        cuuint32_t es[2]      = { 1, 1 };
        ((EncodeFn)encode_fn)(&tmap_b, CU_TENSOR_MAP_DATA_TYPE_FLOAT16, 2, wa,
                              dims, strides, box, es,
                              CU_TENSOR_MAP_INTERLEAVE_NONE, CU_TENSOR_MAP_SWIZZLE_128B,
                              CU_TENSOR_MAP_L2_PROMOTION_L2_128B,
                              CU_TENSOR_MAP_FLOAT_OOB_FILL_NONE);
    }

    cudaFuncSetAttribute(gates_gemm, cudaFuncAttributeMaxDynamicSharedMemorySize, DYN_SMEM);

    prep<<<(MTOT * DD / 4) / 256 + 384, 256>>>(x, Wz, Wf, Wo);
    gates_gemm<<<GRID_P, 256, DYN_SMEM>>>(tmap_a, tmap_b, bz, bfv, bo);
    seg_reduce<<<(BB * NSEG * DD / 2) / 256, 256>>>();
    seg_carry<<<(BB * DD) / 256, 256>>>();
    seg_apply<<<(BB * NSEG * DD / 2) / 256, 256>>>(out);
}

// round 17
// speedup vs baseline: 1.4604x; 1.4604x over previous
#include <cuda_runtime.h>
#include <cuda.h>
#include <cuda_fp16.h>
#include <cstdint>
#include <cmath>

// Problem constants
#define BB   8
#define TT   4096
#define DD   256
#define MTOT (BB*TT)        // 32768
#define KTOT 512            // 2 taps x 256
#define NSEG 256
#define SEGL (TT/NSEG)      // 16

// GEMM tiling: fp16, BK=64 halves, R11 consumer geometry, TMA producer, persistent
#define BM 128
#define BN 128
#define NKB 8               // stages per tile
#define STAGES 3
#define A_BYTES (BM*128)            // 16384
#define B_BYTES (BN*128)            // 16384
#define STAGE_BYTES (A_BYTES+B_BYTES)   // 32768
#define STAGE_TX STAGE_BYTES
#define DYN_SMEM (STAGES*STAGE_BYTES + 1024)   // 99328; 2 CTAs/SM

#define NTILE_N 6
#define NTILES  (NTILE_N * (MTOT/BM))   // 1536
#define GRID_P  296                      // 2 CTAs x 148 SMs
#define EXTRA   (NTILES - 5*GRID_P)      // 56 CTAs do 6 tiles, rest do 5

// ---------------- scratch (device globals) ----------------
__device__ __half g_zh[(size_t)MTOT*DD];
__device__ __half g_fh[(size_t)MTOT*DD];
__device__ __half g_oh[(size_t)MTOT*DD];
__device__ __half g_xh[(size_t)MTOT*DD];
__device__ __half g_wh[3*DD*KTOT];
__device__ float  g_segA[BB*NSEG*DD];
__device__ float  g_segB[BB*NSEG*DD];
__device__ float  g_carry[BB*NSEG*DD];

// ---------------- helpers ----------------
__device__ __forceinline__ uint32_t smem_u32(const void* p) {
    uint32_t a;
    asm("{ .reg .u64 t; cvta.to.shared.u64 t, %1; cvt.u32.u64 %0, t; }" : "=r"(a) : "l"(p));
    return a;
}
__device__ __forceinline__ void ldsm4(uint32_t& r0, uint32_t& r1, uint32_t& r2, uint32_t& r3,
                                      uint32_t addr) {
    asm volatile("ldmatrix.sync.aligned.m8n8.x4.shared.b16 {%0,%1,%2,%3}, [%4];"
                 : "=r"(r0), "=r"(r1), "=r"(r2), "=r"(r3) : "r"(addr));
}
__device__ __forceinline__ void mma_f16(float c[4], const uint32_t a[4], const uint32_t b[2]) {
    asm("mma.sync.aligned.m16n8k16.row.col.f32.f16.f16.f32 "
        "{%0,%1,%2,%3}, {%4,%5,%6,%7}, {%8,%9}, {%0,%1,%2,%3};"
        : "+f"(c[0]), "+f"(c[1]), "+f"(c[2]), "+f"(c[3])
        : "r"(a[0]), "r"(a[1]), "r"(a[2]), "r"(a[3]), "r"(b[0]), "r"(b[1]));
}
__device__ __forceinline__ void tma_load_2d(uint32_t dst, const void* map, int x, int y,
                                            uint32_t mbar) {
    asm volatile(
        "cp.async.bulk.tensor.2d.shared::cta.global.tile.mbarrier::complete_tx::bytes "
        "[%0], [%1, {%2, %3}], [%4];"
        :: "r"(dst), "l"(map), "r"(x), "r"(y), "r"(mbar) : "memory");
}
#define MBARRIER_INIT(addr, cnt) \
    asm volatile("mbarrier.init.shared.b64 [%0], %1;" :: "r"(addr), "r"(cnt) : "memory")
#define MBARRIER_EXPECT_TX(addr, bytes) \
    asm volatile("mbarrier.arrive.expect_tx.shared.b64 _, [%0], %1;" \
                 :: "r"(addr), "r"(bytes) : "memory")
#define FENCE_PROXY_ASYNC() \
    asm volatile("fence.proxy.async.shared::cta;" ::: "memory")
#define MBARRIER_WAIT_PARITY(addr, par) do {                                     \
    uint32_t _m = (addr), _p = (par), _done;                                     \
    asm volatile("{ .reg .pred p; mbarrier.try_wait.parity.acquire.cta.shared::cta.b64 p, [%1], %2;" \
                 " selp.b32 %0, 1, 0, p; }" : "=r"(_done) : "r"(_m), "r"(_p) : "memory"); \
    if (!_done) {                                                                \
        asm volatile("{ .reg .pred P1; WL%=:"                                    \
                     " mbarrier.try_wait.parity.acquire.cta.shared::cta.b64 P1, [%0], %1, 0x989680;" \
                     " @P1 bra.uni WD%=; bra.uni WL%=; WD%=: }"                  \
                     :: "r"(_m), "r"(_p) : "memory");                            \
    } } while (0)

// ---------------- fused prep: x->fp16  +  W transpose->fp16 ----------------
__global__ void prep(const float* __restrict__ x, const float* __restrict__ Wz,
                     const float* __restrict__ Wf, const float* __restrict__ Wo) {
    __shared__ float t[32][33];
    const int bidx = blockIdx.x;
    const int tid  = threadIdx.x;
    if (bidx < (MTOT * DD / 4) / 256) {           // 8192 blocks: x conversion
        size_t i = (size_t)bidx * 256 + tid;
        float4 v = ((const float4*)x)[i];
        ((__half2*)g_xh)[i * 2]     = __floats2half2_rn(v.x, v.y);
        ((__half2*)g_xh)[i * 2 + 1] = __floats2half2_rn(v.z, v.w);
        return;
    }
    const int idx = bidx - (MTOT * DD / 4) / 256;
    const int bx = idx & 63, tap = (idx >> 6) & 1, g = idx >> 7;
    const float* W = (g == 0) ? Wz : (g == 1) ? Wf : Wo;
    const int d0 = (bx & 7) * 32;
    const int n0 = (bx >> 3) * 32;
    const int tx = tid & 31, ty = tid >> 5;
    #pragma unroll
    for (int r = 0; r < 4; r++) {
        int d = d0 + ty + r * 8;
        t[ty + r * 8][tx] = W[(size_t)tap * 65536 + (size_t)d * 256 + n0 + tx];
    }
    __syncthreads();
    #pragma unroll
    for (int r = 0; r < 4; r++) {
        int n = n0 + ty + r * 8;
        g_wh[(size_t)g * (DD * KTOT) + (size_t)n * KTOT + tap * 256 + d0 + tx] =
            __float2half_rn(t[tx][ty + r * 8]);
    }
}

// ---------------- persistent TMA-fed fp16 mma.sync gate GEMM (R16 verbatim) ----------------
__global__ __launch_bounds__(256)
void gates_gemm(const __grid_constant__ CUtensorMap tma_a,
                const __grid_constant__ CUtensorMap tma_b,
                const float* __restrict__ bz, const float* __restrict__ bfv,
                const float* __restrict__ bo) {
    extern __shared__ char dyn[];
    __shared__ __align__(8) uint64_t s_mbar[STAGES];
    const uint32_t sbase = (smem_u32(dyn) + 1023u) & ~1023u;
    uint32_t mb[STAGES];
    #pragma unroll
    for (int i = 0; i < STAGES; i++) mb[i] = smem_u32(&s_mbar[i]);

    const int tid  = threadIdx.x;
    const int warp = tid >> 5, lane = tid & 31;
    const int gq = lane >> 2, q = lane & 3;
    const int wm0 = (warp & 1) * 64;
    const int wn0 = (warp >> 1) * 32;
    const int cta = blockIdx.x;
    const int ntl = (cta < EXTRA) ? 6 : 5;
    const int G   = ntl * NKB;

    if (tid == 0) {
        #pragma unroll
        for (int i = 0; i < STAGES; i++) MBARRIER_INIT(mb[i], 1);
    }
    __syncthreads();

    auto issue = [&](int g) {
        const int s  = g % STAGES;
        const int t  = cta + (g >> 3) * GRID_P;
        const int kb = g & 7;
        const int m0 = (t / NTILE_N) * BM;
        MBARRIER_EXPECT_TX(mb[s], STAGE_TX);
        tma_load_2d(sbase + s * STAGE_BYTES, &tma_a,
                    (kb & 3) * 64, m0 - 1 + (kb >> 2), mb[s]);
        tma_load_2d(sbase + s * STAGE_BYTES + A_BYTES, &tma_b,
                    kb * 64, (t % NTILE_N) * 128, mb[s]);
    };

    const int mi1 = (lane >> 3) & 1;
    const int mi2 = lane >> 4;
    const int rr  = lane & 7;

    if (tid == 0) {
        FENCE_PROXY_ASYNC();
        issue(0); issue(1); issue(2);
    }

    int g = 0;
    for (int k = 0; k < ntl; k++) {
        const int t     = cta + k * GRID_P;
        const int n_idx = t % NTILE_N;
        const int m0    = (t / NTILE_N) * BM;
        const int gate  = n_idx >> 1;
        const int n0g   = (n_idx & 1) * 128;
        const bool first_blk = ((m0 & (TT - 1)) == 0);

        float acc[4][4][4];
        #pragma unroll
        for (int mt = 0; mt < 4; mt++)
            #pragma unroll
            for (int nt = 0; nt < 4; nt++)
                #pragma unroll
                for (int i = 0; i < 4; i++) acc[mt][nt][i] = 0.0f;

        #pragma unroll 1
        for (int kb = 0; kb < NKB; kb++, g++) {
            const int s = g % STAGES;
            MBARRIER_WAIT_PARITY(mb[s], (g / STAGES) & 1);
            if (first_blk && kb < 4) {
                if (tid < 8) {
                    const uint32_t a0 = sbase + s * STAGE_BYTES + (tid << 4);
                    asm volatile("st.shared.v4.b32 [%0], {%1,%1,%1,%1};"
                                 :: "r"(a0), "r"(0) : "memory");
                }
                __syncthreads();
            }
            {
                const uint32_t ab = sbase + s * STAGE_BYTES;
                const uint32_t bb = ab + A_BYTES;
                #pragma unroll
                for (int ks = 0; ks < 4; ks++) {
                    uint32_t af[4][4], bf[4][2];
                    #pragma unroll
                    for (int mt = 0; mt < 4; mt++) {
                        int row = wm0 + mt * 16 + mi1 * 8 + rr;
                        int k4  = ks * 2 + mi2;
                        uint32_t addr = ab + (row << 7) + ((k4 ^ (row & 7)) << 4);
                        ldsm4(af[mt][0], af[mt][1], af[mt][2], af[mt][3], addr);
                    }
                    #pragma unroll
                    for (int ntp = 0; ntp < 2; ntp++) {
                        int row = wn0 + ntp * 16 + mi2 * 8 + rr;
                        int k4  = ks * 2 + mi1;
                        uint32_t addr = bb + (row << 7) + ((k4 ^ (row & 7)) << 4);
                        uint32_t r0, r1, r2, r3;
                        ldsm4(r0, r1, r2, r3, addr);
                        bf[2*ntp][0] = r0;   bf[2*ntp][1] = r1;
                        bf[2*ntp+1][0] = r2; bf[2*ntp+1][1] = r3;
                    }
                    #pragma unroll
                    for (int mt = 0; mt < 4; mt++)
                        #pragma unroll
                        for (int nt = 0; nt < 4; nt++)
                            mma_f16(acc[mt][nt], af[mt], bf[nt]);
                }
            }
            __syncthreads();
            if (tid == 0 && g + STAGES < G) {
                FENCE_PROXY_ASYNC();
                issue(g + STAGES);
            }
        }

        const float* bias = (gate == 0) ? bz : (gate == 1) ? bfv : bo;
        __half* dst       = (gate == 0) ? g_zh : (gate == 1) ? g_fh : g_oh;
        #pragma unroll
        for (int mt = 0; mt < 4; mt++) {
            #pragma unroll
            for (int nt = 0; nt < 4; nt++) {
                #pragma unroll
                for (int h = 0; h < 2; h++) {
                    int m  = m0 + wm0 + mt * 16 + gq + h * 8;
                    int n  = n0g + wn0 + nt * 8 + q * 2;
                    float v0 = acc[mt][nt][2*h]   + bias[n];
                    float v1 = acc[mt][nt][2*h+1] + bias[n + 1];
                    if (gate == 0) {
                        v0 = __fdividef(2.0f, 1.0f + __expf(-2.0f * v0)) - 1.0f;
                        v1 = __fdividef(2.0f, 1.0f + __expf(-2.0f * v1)) - 1.0f;
                    } else {
                        v0 = __fdividef(1.0f, 1.0f + __expf(-v0));
                        v1 = __fdividef(1.0f, 1.0f + __expf(-v1));
                    }
                    *(__half2*)(dst + (size_t)m * DD + n) = __floats2half2_rn(v0, v1);
                }
            }
        }
    }
}

// ---------------- segmented scan: fp16 gates, fp32 math, NSEG=256 ----------------
__global__ void seg_reduce() {
    int tid = blockIdx.x * 256 + threadIdx.x;   // 262144 threads: (b, s, d2)
    int d2 = tid & 127;
    int s  = (tid >> 7) & (NSEG - 1);
    int b  = tid >> 15;
    size_t base2 = (((size_t)b * TT + (size_t)s * SEGL) * DD) / 2 + d2;
    float Ax = 1.0f, Ay = 1.0f, Bx = 0.0f, By = 0.0f;
    #pragma unroll
    for (int i = 0; i < SEGL; i++) {
        float2 f = __half22float2(((const __half2*)g_fh)[base2 + (size_t)i * (DD/2)]);
        float2 z = __half22float2(((const __half2*)g_zh)[base2 + (size_t)i * (DD/2)]);
        Ax *= f.x; Ay *= f.y;
        Bx = f.x * Bx + (1.0f - f.x) * z.x;
        By = f.y * By + (1.0f - f.y) * z.y;
    }
    int sidx = (b * NSEG + s) * (DD/2) + d2;
    ((float2*)g_segA)[sidx] = make_float2(Ax, Ay);
    ((float2*)g_segB)[sidx] = make_float2(Bx, By);
}

// carry: chunked register prefetch — loads of chunk k+1 overlap FFMA chain of chunk k
#define CCH 8
__global__ void seg_carry() {
    int tid = blockIdx.x * 256 + threadIdx.x;   // 2048 threads: (b, d)
    int d = tid & 255;
    int b = tid >> 8;
    const size_t base = (size_t)b * NSEG * DD + d;
    float A[CCH], Bv[CCH], An[CCH], Bn[CCH];
    #pragma unroll
    for (int j = 0; j < CCH; j++) {
        A[j]  = g_segA[base + (size_t)j * DD];
        Bv[j] = g_segB[base + (size_t)j * DD];
    }
    float c = 0.0f;
    #pragma unroll 1
    for (int ch = 0; ch < NSEG / CCH; ch++) {
        if (ch + 1 < NSEG / CCH) {
            const size_t nb = base + (size_t)(ch + 1) * CCH * DD;
            #pragma unroll
            for (int j = 0; j < CCH; j++) {
                An[j] = g_segA[nb + (size_t)j * DD];
                Bn[j] = g_segB[nb + (size_t)j * DD];
            }
        }
        const size_t cb = base + (size_t)ch * CCH * DD;
        #pragma unroll
        for (int j = 0; j < CCH; j++) {
            g_carry[cb + (size_t)j * DD] = c;
            c = A[j] * c + Bv[j];
        }
        #pragma unroll
        for (int j = 0; j < CCH; j++) { A[j] = An[j]; Bv[j] = Bn[j]; }
    }
}

__global__ void seg_apply(float* __restrict__ out) {
    int tid = blockIdx.x * 256 + threadIdx.x;   // 262144 threads: (b, s, d2)
    int d2 = tid & 127;
    int s  = (tid >> 7) & (NSEG - 1);
    int b  = tid >> 15;
    size_t base2 = (((size_t)b * TT + (size_t)s * SEGL) * DD) / 2 + d2;
    float2 c = ((const float2*)g_carry)[(b * NSEG + s) * (DD/2) + d2];
    #pragma unroll
    for (int i = 0; i < SEGL; i++) {
        size_t idx = base2 + (size_t)i * (DD/2);
        float2 f = __half22float2(((const __half2*)g_fh)[idx]);
        float2 z = __half22float2(((const __half2*)g_zh)[idx]);
        float2 o = __half22float2(((const __half2*)g_oh)[idx]);
        c.x = f.x * c.x + (1.0f - f.x) * z.x;
        c.y = f.y * c.y + (1.0f - f.y) * z.y;
        ((float2*)out)[idx] = make_float2(o.x * c.x, o.y * c.y);
    }
}

// ---------------- launch ----------------
typedef CUresult (*EncodeFn)(CUtensorMap*, CUtensorMapDataType, cuuint32_t, void*,
                             const cuuint64_t*, const cuuint64_t*, const cuuint32_t*,
                             const cuuint32_t*, CUtensorMapInterleave, CUtensorMapSwizzle,
                             CUtensorMapL2promotion, CUtensorMapFloatOOBfill);

extern "C" void kernel_launch(void* const* d_in, const int* in_sizes, int n_in,
                              void* d_out, int out_size) {
    const float* x   = (const float*)d_in[0];
    const float* Wz  = (const float*)d_in[1];
    const float* Wf  = (const float*)d_in[2];
    const float* Wo  = (const float*)d_in[3];
    const float* bz  = (const float*)d_in[4];
    const float* bfv = (const float*)d_in[5];
    const float* bo  = (const float*)d_in[6];
    float* out = (float*)d_out;

    void* encode_fn = nullptr;
    cudaDriverEntryPointQueryResult qr;
    cudaGetDriverEntryPointByVersion("cuTensorMapEncodeTiled", &encode_fn, 12000,
                                     cudaEnableDefault, &qr);
    void *xa = nullptr, *wa = nullptr;
    cudaGetSymbolAddress(&xa, g_xh);
    cudaGetSymbolAddress(&wa, g_wh);

    CUtensorMap tmap_a, tmap_b;
    {
        cuuint64_t dims[2]    = { 256, 32768 };
        cuuint64_t strides[1] = { 256 * 2 };
        cuuint32_t box[2]     = { 64, 128 };
        cuuint32_t es[2]      = { 1, 1 };
        ((EncodeFn)encode_fn)(&tmap_a, CU_TENSOR_MAP_DATA_TYPE_FLOAT16, 2, xa,
                              dims, strides, box, es,
                              CU_TENSOR_MAP_INTERLEAVE_NONE, CU_TENSOR_MAP_SWIZZLE_128B,
                              CU_TENSOR_MAP_L2_PROMOTION_L2_128B,
                              CU_TENSOR_MAP_FLOAT_OOB_FILL_NONE);
    }
    {
        cuuint64_t dims[2]    = { 512, 768 };
        cuuint64_t strides[1] = { 512 * 2 };
        cuuint32_t box[2]     = { 64, 128 };
        cuuint32_t es[2]      = { 1, 1 };
        ((EncodeFn)encode_fn)(&tmap_b, CU_TENSOR_MAP_DATA_TYPE_FLOAT16, 2, wa,
                              dims, strides, box, es,
                              CU_TENSOR_MAP_INTERLEAVE_NONE, CU_TENSOR_MAP_SWIZZLE_128B,
                              CU_TENSOR_MAP_L2_PROMOTION_L2_128B,
                              CU_TENSOR_MAP_FLOAT_OOB_FILL_NONE);
    }

    cudaFuncSetAttribute(gates_gemm, cudaFuncAttributeMaxDynamicSharedMemorySize, DYN_SMEM);

    prep<<<(MTOT * DD / 4) / 256 + 384, 256>>>(x, Wz, Wf, Wo);
    gates_gemm<<<GRID_P, 256, DYN_SMEM>>>(tmap_a, tmap_b, bz, bfv, bo);
    seg_reduce<<<(BB * NSEG * DD / 2) / 256, 256>>>();
    seg_carry<<<(BB * DD) / 256, 256>>>();
    seg_apply<<<(BB * NSEG * DD / 2) / 256, 256>>>(out);
}